// round 9
// baseline (speedup 1.0000x reference)
#include <cuda_runtime.h>

// Problem shape: H=1080, W=1920 (n_pix = 2,073,600, divisible by 4), S=2000, C=8.
// Output (float32): [1,1,H,W] preseg followed by [7,4,H,W] attmaps, flattened.

#define NCLS 8
#define NJ   7          // classes 2..8 -> j = 1..7
#define ROWW 32         // padded table row width (floats), 128B-aligned rows

// Per-superpixel precomputed table. Row layout (floats):
//   [jj*4+0] = knn[j]            (j = jj+1)
//   [jj*4+1] = max_{k!=j} knn
//   [jj*4+2] = cent[j]
//   [jj*4+3] = max_{k!=j} cent
//   [28]     = (float)knn_pred
// 4096 rows of headroom; S=2000 actually used. 512 KB static device array.
__device__ __align__(16) float g_table[4096 * ROWW];

__global__ void build_table_kernel(const int* __restrict__ pred,
                                   const float* __restrict__ knn,
                                   const float* __restrict__ cent,
                                   int S) {
    int s = blockIdx.x * blockDim.x + threadIdx.x;
    if (s >= S) return;

    float k[NCLS], c[NCLS];
#pragma unroll
    for (int j = 0; j < NCLS; j++) {
        k[j] = knn[(size_t)s * NCLS + j];
        c[j] = cent[(size_t)s * NCLS + j];
    }

    // max / argmax / second-max for each table
    float km1 = k[0], km2 = -__int_as_float(0x7f800000); // -inf
    int   ka  = 0;
#pragma unroll
    for (int j = 1; j < NCLS; j++) {
        if (k[j] > km1) { km2 = km1; km1 = k[j]; ka = j; }
        else if (k[j] > km2) { km2 = k[j]; }
    }
    float cm1 = c[0], cm2 = -__int_as_float(0x7f800000);
    int   ca  = 0;
#pragma unroll
    for (int j = 1; j < NCLS; j++) {
        if (c[j] > cm1) { cm2 = cm1; cm1 = c[j]; ca = j; }
        else if (c[j] > cm2) { cm2 = c[j]; }
    }

    float* row = g_table + (size_t)s * ROWW;
#pragma unroll
    for (int jj = 0; jj < NJ; jj++) {
        int j = jj + 1;
        row[jj * 4 + 0] = k[j];
        row[jj * 4 + 1] = (j == ka) ? km2 : km1;  // exact leave-one-out max
        row[jj * 4 + 2] = c[j];
        row[jj * 4 + 3] = (j == ca) ? cm2 : cm1;
    }
    row[28] = (float)pred[s];
    row[29] = 0.f; row[30] = 0.f; row[31] = 0.f;
}

// 4 pixels per thread: 1 int4 label load, 4x7 aligned float4 table gathers
// (L2-hot, 256 KB table), 29 coalesced STG.128 per thread.
__global__ __launch_bounds__(256) void scatter_kernel(
        const int* __restrict__ spx,
        float* __restrict__ out,
        int n4, int n_pix) {
    int t = blockIdx.x * blockDim.x + threadIdx.x;
    if (t >= n4) return;

    int4 lab = reinterpret_cast<const int4*>(spx)[t];
    const float* b0 = g_table + (size_t)(lab.x - 1) * ROWW;
    const float* b1 = g_table + (size_t)(lab.y - 1) * ROWW;
    const float* b2 = g_table + (size_t)(lab.z - 1) * ROWW;
    const float* b3 = g_table + (size_t)(lab.w - 1) * ROWW;

    size_t p = (size_t)t * 4;

    // preseg plane (plane 0)
    float4 ps = make_float4(__ldg(b0 + 28), __ldg(b1 + 28),
                            __ldg(b2 + 28), __ldg(b3 + 28));
    *reinterpret_cast<float4*>(out + p) = ps;

    // 28 attmap planes: plane index (jj*4 + m), base offset n_pix
    float* o = out + (size_t)n_pix + p;
#pragma unroll
    for (int g = 0; g < NJ; g++) {
        float4 a  = __ldg(reinterpret_cast<const float4*>(b0) + g);
        float4 bb = __ldg(reinterpret_cast<const float4*>(b1) + g);
        float4 cc = __ldg(reinterpret_cast<const float4*>(b2) + g);
        float4 d  = __ldg(reinterpret_cast<const float4*>(b3) + g);
        *reinterpret_cast<float4*>(o + (size_t)(4 * g + 0) * n_pix) =
            make_float4(a.x, bb.x, cc.x, d.x);
        *reinterpret_cast<float4*>(o + (size_t)(4 * g + 1) * n_pix) =
            make_float4(a.y, bb.y, cc.y, d.y);
        *reinterpret_cast<float4*>(o + (size_t)(4 * g + 2) * n_pix) =
            make_float4(a.z, bb.z, cc.z, d.z);
        *reinterpret_cast<float4*>(o + (size_t)(4 * g + 3) * n_pix) =
            make_float4(a.w, bb.w, cc.w, d.w);
    }
}

extern "C" void kernel_launch(void* const* d_in, const int* in_sizes, int n_in,
                              void* d_out, int out_size) {
    const int*   spx  = (const int*)d_in[0];    // [1,1,H,W] int32, labels 1..S
    const int*   pred = (const int*)d_in[1];    // [S] int32, labels 1..C
    const float* knn  = (const float*)d_in[2];  // [S,C] float32
    const float* cent = (const float*)d_in[3];  // [S,C] float32
    float* out = (float*)d_out;

    int n_pix = in_sizes[0];   // H*W = 2,073,600
    int S     = in_sizes[1];   // 2000

    build_table_kernel<<<(S + 255) / 256, 256>>>(pred, knn, cent, S);

    int n4 = n_pix / 4;        // n_pix divisible by 4 for this problem
    scatter_kernel<<<(n4 + 255) / 256, 256>>>(spx, out, n4, n_pix);
}

// round 10
// speedup vs baseline: 1.6088x; 1.6088x over previous
#include <cuda_runtime.h>

// Problem shape: H=1080, W=1920 (n_pix = 2,073,600, divisible by 4), S=2000, C=8.
// Output (float32): [1,1,H,W] preseg followed by [7,4,H,W] attmaps, flattened.
//
// Strategy: one fused kernel, 1 CTA/SM, full per-superpixel table resident in
// shared memory (S*29 floats = 232,000 B < 232,448 B limit). Random per-pixel
// gathers hit the smem crossbar instead of generating L1tex wavefronts.

#define NCLS 8
#define NJ   7          // classes 2..8 -> j = 1..7

__global__ __launch_bounds__(1024, 1)
void fused_scatter_kernel(const int* __restrict__ spx,
                          const int* __restrict__ pred,
                          const float* __restrict__ knn,
                          const float* __restrict__ cent,
                          float* __restrict__ out,
                          int S, int n4, int n_pix)
{
    extern __shared__ float smem[];
    float* att = smem;                       // S rows x 28 floats (112B, 16B-aligned)
    float* prd = smem + (size_t)S * 28;      // S floats

    const float NEG_INF = -__int_as_float(0x7f800000);

    // ---- Phase 1: build the compact table in smem (L2-hot inputs) ----
    for (int s = threadIdx.x; s < S; s += blockDim.x) {
        float4 k0 = __ldg((const float4*)knn  + (size_t)s * 2);
        float4 k1 = __ldg((const float4*)knn  + (size_t)s * 2 + 1);
        float4 c0 = __ldg((const float4*)cent + (size_t)s * 2);
        float4 c1 = __ldg((const float4*)cent + (size_t)s * 2 + 1);
        float k[NCLS] = {k0.x, k0.y, k0.z, k0.w, k1.x, k1.y, k1.z, k1.w};
        float c[NCLS] = {c0.x, c0.y, c0.z, c0.w, c1.x, c1.y, c1.z, c1.w};

        // max / argmax / second-max -> exact leave-one-out max
        float km1 = k[0], km2 = NEG_INF; int ka = 0;
#pragma unroll
        for (int j = 1; j < NCLS; j++) {
            if (k[j] > km1)      { km2 = km1; km1 = k[j]; ka = j; }
            else if (k[j] > km2) { km2 = k[j]; }
        }
        float cm1 = c[0], cm2 = NEG_INF; int ca = 0;
#pragma unroll
        for (int j = 1; j < NCLS; j++) {
            if (c[j] > cm1)      { cm2 = cm1; cm1 = c[j]; ca = j; }
            else if (c[j] > cm2) { cm2 = c[j]; }
        }

        float4* row = (float4*)(att + (size_t)s * 28);
#pragma unroll
        for (int jj = 0; jj < NJ; jj++) {
            int j = jj + 1;
            row[jj] = make_float4(k[j], (j == ka) ? km2 : km1,
                                  c[j], (j == ca) ? cm2 : cm1);
        }
        prd[s] = (float)__ldg(pred + s);
    }
    __syncthreads();

    // ---- Phase 2: stream pixels, 4 per thread, gathers from smem ----
    int stride = gridDim.x * blockDim.x;
    for (int t = blockIdx.x * blockDim.x + threadIdx.x; t < n4; t += stride) {
        int4 lab = __ldcs((const int4*)spx + t);
        const float4* r0 = (const float4*)(att + (size_t)(lab.x - 1) * 28);
        const float4* r1 = (const float4*)(att + (size_t)(lab.y - 1) * 28);
        const float4* r2 = (const float4*)(att + (size_t)(lab.z - 1) * 28);
        const float4* r3 = (const float4*)(att + (size_t)(lab.w - 1) * 28);

        size_t p = (size_t)t * 4;

        // preseg plane
        float4 ps = make_float4(prd[lab.x - 1], prd[lab.y - 1],
                                prd[lab.z - 1], prd[lab.w - 1]);
        __stcs((float4*)(out + p), ps);

        // 28 attmap planes (plane index 4*g + m), base offset n_pix
        float* o = out + (size_t)n_pix + p;
#pragma unroll
        for (int g = 0; g < NJ; g++) {
            float4 a  = r0[g];
            float4 b  = r1[g];
            float4 cc = r2[g];
            float4 d  = r3[g];
            __stcs((float4*)(o + (size_t)(4 * g + 0) * n_pix),
                   make_float4(a.x, b.x, cc.x, d.x));
            __stcs((float4*)(o + (size_t)(4 * g + 1) * n_pix),
                   make_float4(a.y, b.y, cc.y, d.y));
            __stcs((float4*)(o + (size_t)(4 * g + 2) * n_pix),
                   make_float4(a.z, b.z, cc.z, d.z));
            __stcs((float4*)(o + (size_t)(4 * g + 3) * n_pix),
                   make_float4(a.w, b.w, cc.w, d.w));
        }
    }
}

extern "C" void kernel_launch(void* const* d_in, const int* in_sizes, int n_in,
                              void* d_out, int out_size) {
    const int*   spx  = (const int*)d_in[0];    // [1,1,H,W] int32, labels 1..S
    const int*   pred = (const int*)d_in[1];    // [S] int32, labels 1..C
    const float* knn  = (const float*)d_in[2];  // [S,C] float32
    const float* cent = (const float*)d_in[3];  // [S,C] float32
    float* out = (float*)d_out;

    int n_pix = in_sizes[0];   // H*W = 2,073,600
    int S     = in_sizes[1];   // 2000
    int n4    = n_pix / 4;

    size_t smem_bytes = (size_t)S * 29 * sizeof(float);  // 232,000 B

    cudaFuncSetAttribute(fused_scatter_kernel,
                         cudaFuncAttributeMaxDynamicSharedMemorySize,
                         (int)smem_bytes);

    int nsm = 148;
    cudaDeviceGetAttribute(&nsm, cudaDevAttrMultiProcessorCount, 0);

    fused_scatter_kernel<<<nsm, 1024, smem_bytes>>>(
        spx, pred, knn, cent, out, S, n4, n_pix);
}